// round 1
// baseline (speedup 1.0000x reference)
#include <cuda_runtime.h>

// LatentQuantizer: VQ codebook quantization.
// Inputs (metadata order): latents [N*64] f32, scaler [N] f32, redshift [N] f32,
//                          codebook_weight [64*1024] f32 (D-major, E contiguous)
// Output (f32, concatenated tuple order):
//   z_q_st [N*64], scaler [N], redshift [N], codebook_loss [1], min_embed_ids [N]

#define DIMS   64
#define NEMB   1024
#define ETILE  512
#define TPB    256
#define SMEM_BYTES ((ETILE * DIMS + NEMB) * 4)   // 128KB W tile + 4KB wnorm

// Scratch (device globals; no allocations allowed)
__device__ __align__(16) float  g_Wt[NEMB * DIMS];   // e-major transpose of W
__device__            float  g_wnorm[NEMB];
__device__            double g_loss;

// ---------------------------------------------------------------------------
// f32x2 packed helpers (Blackwell packed fp32: 2x FFMA throughput per issue)
// ---------------------------------------------------------------------------
__device__ __forceinline__ unsigned long long ffma2(unsigned long long a,
                                                    unsigned long long b,
                                                    unsigned long long c) {
    unsigned long long d;
    asm("fma.rn.f32x2 %0, %1, %2, %3;" : "=l"(d) : "l"(a), "l"(b), "l"(c));
    return d;
}
__device__ __forceinline__ float f2lo(unsigned long long v) {
    return __uint_as_float((unsigned)(v & 0xffffffffull));
}
__device__ __forceinline__ float f2hi(unsigned long long v) {
    return __uint_as_float((unsigned)(v >> 32));
}

// ---------------------------------------------------------------------------
// prep: zero loss acc, wnorm[e] = sum_d W[d][e]^2, transpose W -> Wt[e][d]
// ---------------------------------------------------------------------------
__global__ void prep_kernel(const float* __restrict__ W) {
    int e = blockIdx.x * blockDim.x + threadIdx.x;
    if (e == 0) g_loss = 0.0;
    if (e < NEMB) {
        float col[DIMS];
        float s = 0.f;
        #pragma unroll
        for (int d = 0; d < DIMS; ++d) {
            float v = W[d * NEMB + e];   // coalesced across e
            col[d] = v;
            s += v * v;
        }
        g_wnorm[e] = s;
        float4* dst = (float4*)(g_Wt + (size_t)e * DIMS);
        #pragma unroll
        for (int i = 0; i < DIMS / 4; ++i)
            dst[i] = make_float4(col[4*i], col[4*i+1], col[4*i+2], col[4*i+3]);
    }
}

// ---------------------------------------------------------------------------
// main: one row per thread; W tiles staged in smem; packed-f32x2 dot products
// ---------------------------------------------------------------------------
__global__ __launch_bounds__(TPB, 1) void vq_kernel(
    const float* __restrict__ latents,
    const float* __restrict__ scaler,
    const float* __restrict__ redshift,
    float* __restrict__ out,
    int N)
{
    extern __shared__ float smem[];
    float* sW  = smem;                  // [ETILE][DIMS]
    float* swn = smem + ETILE * DIMS;   // [NEMB]

    const int tid = threadIdx.x;
    const long long r = (long long)blockIdx.x * TPB + tid;
    const bool active = (r < N);

    // wnorm -> smem (whole table, once)
    for (int i = tid; i < NEMB; i += TPB) swn[i] = g_wnorm[i];

    // Load this thread's latent row as 32 packed f32x2 values; compute ||z||^2
    unsigned long long z2[DIMS / 2];
    float zn = 0.f;
    if (active) {
        const ulonglong2* zr = (const ulonglong2*)(latents + r * DIMS);
        #pragma unroll
        for (int i = 0; i < DIMS / 4; ++i) {
            ulonglong2 v = zr[i];
            z2[2*i]   = v.x;
            z2[2*i+1] = v.y;
        }
        #pragma unroll
        for (int i = 0; i < DIMS / 2; ++i) {
            float lo = f2lo(z2[i]), hi = f2hi(z2[i]);
            zn += lo * lo;
            zn += hi * hi;
        }
    } else {
        #pragma unroll
        for (int i = 0; i < DIMS / 2; ++i) z2[i] = 0ull;
    }

    float best  = 3.402823466e38f;
    int   bestE = 0;

    for (int t = 0; t < NEMB / ETILE; ++t) {
        __syncthreads();  // previous tile fully consumed
        {   // cooperative coalesced tile fill: 128KB, float4 granularity
            const float4* src = (const float4*)(g_Wt + (size_t)t * ETILE * DIMS);
            float4* dst = (float4*)sW;
            #pragma unroll 4
            for (int i = tid; i < ETILE * DIMS / 4; i += TPB) dst[i] = src[i];
        }
        __syncthreads();

        #pragma unroll 1
        for (int e = 0; e < ETILE; ++e) {
            const ulonglong2* w2 = (const ulonglong2*)(sW + (size_t)e * DIMS);
            unsigned long long a0 = 0ull, a1 = 0ull, a2 = 0ull, a3 = 0ull;
            #pragma unroll
            for (int i = 0; i < 8; ++i) {       // 4 independent FMA chains
                ulonglong2 wa = w2[2*i];
                ulonglong2 wb = w2[2*i + 1];
                a0 = ffma2(z2[4*i],     wa.x, a0);
                a1 = ffma2(z2[4*i + 1], wa.y, a1);
                a2 = ffma2(z2[4*i + 2], wb.x, a2);
                a3 = ffma2(z2[4*i + 3], wb.y, a3);
            }
            float dot = ((f2lo(a0) + f2hi(a0)) + (f2lo(a1) + f2hi(a1)))
                      + ((f2lo(a2) + f2hi(a2)) + (f2lo(a3) + f2hi(a3)));
            // EXACT reference association order: (||z||^2 - 2*dot) + ||w||^2
            float dd = (zn - 2.0f * dot) + swn[t * ETILE + e];
            if (dd < best) { best = dd; bestE = t * ETILE + e; }  // first-index ties
        }
    }

    // ---- epilogue ----
    float lsum = 0.f;
    if (active) {
        const float4* wq = (const float4*)(g_Wt + (size_t)bestE * DIMS);
        float4* oz = (float4*)(out + r * DIMS);
        #pragma unroll
        for (int i = 0; i < DIMS / 4; ++i) {
            float4 w = wq[i];
            float za = f2lo(z2[2*i]),     zb = f2hi(z2[2*i]);
            float zc = f2lo(z2[2*i + 1]), zd = f2hi(z2[2*i + 1]);
            float d0 = w.x - za, d1 = w.y - zb, d2 = w.z - zc, d3 = w.w - zd;
            lsum += d0*d0 + d1*d1 + d2*d2 + d3*d3;
            // straight-through estimator exactly as reference: z + (z_q - z)
            oz[i] = make_float4(za + d0, zb + d1, zc + d2, zd + d3);
        }
        long long oScaler = (long long)N * DIMS;
        long long oRed    = oScaler + N;
        long long oIds    = oScaler + 2LL * N + 1;   // after the loss scalar
        out[oScaler + r] = scaler[r];
        out[oRed    + r] = redshift[r];
        out[oIds    + r] = (float)bestE;
    }

    // block-reduce loss partial -> double accumulator
    #pragma unroll
    for (int o = 16; o > 0; o >>= 1)
        lsum += __shfl_down_sync(0xffffffffu, lsum, o);
    __shared__ float warpsum[TPB / 32];
    if ((tid & 31) == 0) warpsum[tid >> 5] = lsum;
    __syncthreads();
    if (tid < TPB / 32) {
        float v = warpsum[tid];
        #pragma unroll
        for (int o = (TPB / 64); o > 0; o >>= 1)
            v += __shfl_down_sync(0xffu, v, o);
        if (tid == 0) atomicAdd(&g_loss, (double)v);
    }
}

// ---------------------------------------------------------------------------
// finalize: loss = (1 + BETA) * mean((z_q - z)^2),  BETA = 0.25
// ---------------------------------------------------------------------------
__global__ void finalize_kernel(float* __restrict__ out, long long off, double scale) {
    out[off] = (float)(g_loss * scale);
}

// ---------------------------------------------------------------------------
extern "C" void kernel_launch(void* const* d_in, const int* in_sizes, int n_in,
                              void* d_out, int out_size) {
    const float* latents  = (const float*)d_in[0];
    const float* scaler   = (const float*)d_in[1];
    const float* redshift = (const float*)d_in[2];
    const float* W        = (const float*)d_in[3];
    float* out = (float*)d_out;
    const int N = in_sizes[1];   // scaler element count

    cudaFuncSetAttribute(vq_kernel, cudaFuncAttributeMaxDynamicSharedMemorySize,
                         SMEM_BYTES);

    prep_kernel<<<(NEMB + 255) / 256, 256>>>(W);
    vq_kernel<<<(N + TPB - 1) / TPB, TPB, SMEM_BYTES>>>(latents, scaler, redshift,
                                                        out, N);
    finalize_kernel<<<1, 1>>>(out, (long long)N * DIMS + 2LL * N,
                              1.25 / ((double)N * (double)DIMS));
}